// round 12
// baseline (speedup 1.0000x reference)
#include <cuda_runtime.h>

// CRF negative log-likelihood, T=512 B=64 L=48, START=46, STOP=47.
// Fused kernel. 96 threads: 2 threads per state (half-dot, 24 i's each).
// Combine via red.shared.add.f32 into a zeroed slot (no shfl on the chain):
//   v_h[j] = (sum_{i in half h} u_i * E[i][j]) * e_j [* ru]
//   buf[t%3][j] = v_0[j] (+RED) v_1[j]      -- exactly u_t[j]
// 3-buffer rotation: read (t-1)%3, RED into t%3, zero (t+1)%3 for next step.
// RESC=6 => tb%3 == 1 always: all phases compile-time.

#define TT 512
#define BB 64
#define LLAB 48
#define START_TAG 46
#define STOP_TAG 47
#define NT 96
#define RESC 6
#define L2E 1.4426950408889634f
#define LN2f 0.6931471805599453f
#define FSTRIDE (BB * LLAB)   // 3072 floats per time step

__device__ float        g_partial[BB];
__device__ unsigned int g_done;       // wraps 0..63 -> self-resetting

__device__ __forceinline__ float ex2_approx(float x) {
    float r; asm("ex2.approx.ftz.f32 %0, %1;" : "=f"(r) : "f"(x)); return r;
}
__device__ __forceinline__ float lg2_approx(float x) {
    float r; asm("lg2.approx.ftz.f32 %0, %1;" : "=f"(r) : "f"(x)); return r;
}
__device__ __forceinline__ float rcp_approx(float x) {
    float r; asm("rcp.approx.ftz.f32 %0, %1;" : "=f"(r) : "f"(x)); return r;
}
__device__ __forceinline__ void red_smem_add(unsigned int addr, float v) {
    asm volatile("red.shared.add.f32 [%0], %1;" :: "r"(addr), "f"(v) : "memory");
}

__device__ __forceinline__ int get_tag(const void* tags, int idx, int is32) {
    int v = is32 ? ((const int*)tags)[idx]
                 : (int)((const long long*)tags)[idx];
    return v < 0 ? 0 : (v > 47 ? 47 : v);
}
__device__ __forceinline__ int get_mask(const void* mask, int idx, int is8) {
    return is8 ? (int)((const unsigned char*)mask)[idx]
               : (((const int*)mask)[idx] != 0);
}

__global__ __launch_bounds__(NT, 1) void crf_fused_kernel(
    const float* __restrict__ feats,      // (T, B, L)
    const float* __restrict__ trans,      // (L, L)
    const void*  __restrict__ candA,
    const void*  __restrict__ candB,
    float*       __restrict__ out)
{
    const int b    = blockIdx.x;
    const int tid  = threadIdx.x;
    const int j    = tid >> 1;    // output state 0..47
    const int h    = tid & 1;     // half of the i-range
    const int w    = tid >> 5;
    const int lane = tid & 31;

    __shared__ __align__(16) float s_z[3][LLAB];   // rotating u buffers
    __shared__ float s_gwarp[3];
    __shared__ float s_red[BB];
    __shared__ float s_gold;
    __shared__ int   s_len;
    __shared__ int   s_flags;
    __shared__ int   s_last;

    const unsigned int zbase =
        (unsigned int)__cvta_generic_to_shared(&s_z[0][0]);

    if (tid == 0) { s_len = 0; s_flags = 0; s_last = 0; }
    __syncthreads();

    // ---------------- buffer identification (one LDG round) ----------------
    {
        const unsigned* ua = (const unsigned*)candA;
        const unsigned* ub = (const unsigned*)candB;
        int f = 0;
        if (ua[tid] & 0xFEFEFEFEu)       f |= 1;   // A has byte >= 2 -> A=tags
        if (ub[tid] & 0xFEFEFEFEu)       f |= 2;
        if (ua[2 * tid + 1] != 0)        f |= 4;   // A odd words nonzero -> i32
        if (ub[2 * tid + 1] != 0)        f |= 8;
        if ((ua[0] & 0x0000FF00u) != 0)  f |= 16;  // 1-byte mask signature
        if ((ub[0] & 0x0000FF00u) != 0)  f |= 32;
        if (f) atomicOr(&s_flags, f);
    }
    __syncthreads();
    const int flags = s_flags;
    const int swap  = !(flags & 1);
    const void* tags = swap ? candB : candA;
    const void* mask = swap ? candA : candB;
    const int is32 = swap ? ((flags >> 3) & 1) : ((flags >> 2) & 1);
    const int is8  = swap ? ((flags >> 4) & 1) : ((flags >> 5) & 1);

    // ---------------- gold path score + length -----------------------------
    {
        float gpart = 0.0f;
        int   lpart = 0;
        for (int t = tid; t < TT; t += NT) {
            if (get_mask(mask, b * TT + t, is8)) {
                lpart++;
                int tag  = get_tag(tags, b * TT + t, is32);
                int prev = (t == 0) ? START_TAG : get_tag(tags, b * TT + t - 1, is32);
                gpart += feats[t * FSTRIDE + b * LLAB + tag]
                       + trans[prev * LLAB + tag];
            }
        }
        #pragma unroll
        for (int off = 16; off > 0; off >>= 1)
            gpart += __shfl_xor_sync(0xffffffffu, gpart, off);  // fixed order
        if (lane == 0) s_gwarp[w] = gpart;
        atomicAdd(&s_len, lpart);
    }

    // ------------- per-thread packed-E column slice (12 x f32x2 = 24 i) -----
    unsigned long long Epk[12];
    #pragma unroll
    for (int r = 0; r < 12; ++r) {
        float e0 = expf(trans[(24 * h + 2 * r)     * LLAB + j]);
        float e1 = expf(trans[(24 * h + 2 * r + 1) * LLAB + j]);
        unsigned long long pk;
        asm("mov.b64 %0, {%1, %2};" : "=l"(pk) : "f"(e0), "f"(e1));
        Epk[r] = pk;
    }

    // ---------------- init: u_0 -> buf0; zero buf1 (step-1 RED target) ------
    const float* fb = feats + b * LLAB;
    float p00 = fb[0] + trans[START_TAG * LLAB + 0];
    float p0j = fb[j] + trans[START_TAG * LLAB + j];
    if (h == 0) {
        s_z[0][j] = ex2_approx((p0j - p00) * L2E);
        s_z[1][j] = 0.0f;
    }
    float Cacc  = p00;
    float Clog2 = 0.0f;

    __syncthreads();
    int len = s_len;
    len = len < 1 ? 1 : (len > TT ? TT : len);
    const int nsteps = len - 1;          // >= 255

    if (tid == 0) {
        int endid = get_tag(tags, b * TT + len - 1, is32);
        s_gold = (s_gwarp[0] + s_gwarp[1] + s_gwarp[2])
               + trans[endid * LLAB + STOP_TAG];
    }

    // ---------------- forward recursion --------------------------------------
    // FIXED prefetch parity: slot 0 <- t=1 (consumed at k=0), slot 1 <- t=2.
    float pfj[2], pf0[2];
    {
        int t1 = (1 <= nsteps) ? 1 : (nsteps < 1 ? 1 : nsteps);
        int t2 = (2 <= nsteps) ? 2 : t1;
        pfj[0] = fb[t1 * FSTRIDE + j];  pf0[0] = fb[t1 * FSTRIDE];
        pfj[1] = fb[t2 * FSTRIDE + j];  pf0[1] = fb[t2 * FSTRIDE];
    }

    const int npad = ((nsteps + RESC - 1) / RESC) * RESC;

    // tb starts at 1, advances by RESC=6 -> tb % 3 == 1 and tb odd always:
    //   phase ph = t%3 = (1+k)%3 (compile-time per k)
    //   feats slot = k&1 (compile-time per k)
    for (int tb = 1; tb <= npad; tb += RESC) {
        #pragma unroll
        for (int k = 0; k < RESC; ++k) {
            const int  t    = tb + k;
            const bool live = (t <= nsteps);          // uniform across block

            const int ph = (1 + k) % 3;               // t % 3
            const int R  = (ph + 2) % 3;              // (t-1) % 3: read
            const int W  = ph;                        // t % 3: RED target
            const int Z  = (ph + 1) % 3;              // (t+1) % 3: zero ahead

            int tp = t + 2; if (tp > nsteps) tp = nsteps; if (tp < 1) tp = 1;
            float nfj = fb[tp * FSTRIDE + j];
            float nf0 = fb[tp * FSTRIDE];

            float fj = pfj[k & 1], f0 = pf0[k & 1];
            float e  = ex2_approx((fj - f0) * L2E);   // pre-bar: hidden

            __syncthreads();                          // buf R combined
            const float* uin = s_z[R];

            // half-dot: 24 elems = 6x LDS.128 + 12 packed FMAs, depth 3
            unsigned long long a0 = 0ULL, a1 = 0ULL, a2 = 0ULL, a3 = 0ULL;
            const ulonglong2* up =
                reinterpret_cast<const ulonglong2*>(uin + 24 * h);
            ulonglong2 q0 = up[0];
            ulonglong2 q1 = up[1];
            ulonglong2 q2 = up[2];
            ulonglong2 q3 = up[3];
            ulonglong2 q4 = up[4];
            ulonglong2 q5 = up[5];
            asm("fma.rn.f32x2 %0, %1, %2, %0;" : "+l"(a0) : "l"(q0.x), "l"(Epk[0]));
            asm("fma.rn.f32x2 %0, %1, %2, %0;" : "+l"(a1) : "l"(q0.y), "l"(Epk[1]));
            asm("fma.rn.f32x2 %0, %1, %2, %0;" : "+l"(a2) : "l"(q1.x), "l"(Epk[2]));
            asm("fma.rn.f32x2 %0, %1, %2, %0;" : "+l"(a3) : "l"(q1.y), "l"(Epk[3]));
            asm("fma.rn.f32x2 %0, %1, %2, %0;" : "+l"(a0) : "l"(q2.x), "l"(Epk[4]));
            asm("fma.rn.f32x2 %0, %1, %2, %0;" : "+l"(a1) : "l"(q2.y), "l"(Epk[5]));
            asm("fma.rn.f32x2 %0, %1, %2, %0;" : "+l"(a2) : "l"(q3.x), "l"(Epk[6]));
            asm("fma.rn.f32x2 %0, %1, %2, %0;" : "+l"(a3) : "l"(q3.y), "l"(Epk[7]));
            asm("fma.rn.f32x2 %0, %1, %2, %0;" : "+l"(a0) : "l"(q4.x), "l"(Epk[8]));
            asm("fma.rn.f32x2 %0, %1, %2, %0;" : "+l"(a1) : "l"(q4.y), "l"(Epk[9]));
            asm("fma.rn.f32x2 %0, %1, %2, %0;" : "+l"(a2) : "l"(q5.x), "l"(Epk[10]));
            asm("fma.rn.f32x2 %0, %1, %2, %0;" : "+l"(a3) : "l"(q5.y), "l"(Epk[11]));

            float u0 = uin[0];                        // scalar broadcast LDS
            float ru = 1.0f, lg = 0.0f;
            if (k == 0) {                             // rescale step
                ru = rcp_approx(u0);
                lg = lg2_approx(u0);
            }

            unsigned long long s01, s23, sall;
            asm("add.rn.f32x2 %0, %1, %2;" : "=l"(s01)  : "l"(a0), "l"(a1));
            asm("add.rn.f32x2 %0, %1, %2;" : "=l"(s23)  : "l"(a2), "l"(a3));
            asm("add.rn.f32x2 %0, %1, %2;" : "=l"(sall) : "l"(s01), "l"(s23));
            float slo, shi;
            asm("mov.b64 {%0, %1}, %2;" : "=f"(slo), "=f"(shi) : "l"(sall));
            float s = slo + shi;                      // this half's partial

            // scale own partial (distributes over the half-sum), then RED.
            // exactly 2 contributions land on a zeroed slot; fadd is
            // commutative -> bitwise deterministic.
            float vh = (k == 0) ? s * e * ru : s * e;
            if (live) {
                red_smem_add(zbase + (unsigned)((W * LLAB + j) * 4), vh);
                if (h == 0) s_z[Z][j] = 0.0f;         // pre-zero next target
                Cacc += f0;                           // off critical path
                if (k == 0) Clog2 += lg;
            }
            pfj[k & 1] = nfj; pf0[k & 1] = nf0;
        }
    }

    __syncthreads();

    // -------- final transition to STOP (single thread, off clock) -----------
    if (tid == 94) {                 // (j=47, h=0)
        const float* uin = s_z[nsteps % 3];
        float a0 = 0.f, a1 = 0.f, a2 = 0.f, a3 = 0.f;
        #pragma unroll
        for (int i = 0; i < LLAB; i += 4) {
            a0 = fmaf(uin[i + 0], expf(trans[(i + 0) * LLAB + STOP_TAG]), a0);
            a1 = fmaf(uin[i + 1], expf(trans[(i + 1) * LLAB + STOP_TAG]), a1);
            a2 = fmaf(uin[i + 2], expf(trans[(i + 2) * LLAB + STOP_TAG]), a2);
            a3 = fmaf(uin[i + 3], expf(trans[(i + 3) * LLAB + STOP_TAG]), a3);
        }
        float s = (a0 + a1) + (a2 + a3);
        float fwd = Cacc + (Clog2 + lg2_approx(s)) * LN2f;
        g_partial[b] = fwd - s_gold;
        __threadfence();
        if (atomicInc(&g_done, BB - 1) == BB - 1) s_last = 1;
    }
    __syncthreads();

    // ---------------- last block: deterministic fixed-order reduction -------
    if (s_last) {
        if (tid < BB) s_red[tid] = __ldcg(&g_partial[tid]);
        __syncthreads();
        if (tid == 0) {
            float v0 = 0.f, v1 = 0.f, v2 = 0.f, v3 = 0.f;
            #pragma unroll
            for (int i = 0; i < BB; i += 4) {
                v0 += s_red[i + 0];
                v1 += s_red[i + 1];
                v2 += s_red[i + 2];
                v3 += s_red[i + 3];
            }
            out[0] = (v0 + v1) + (v2 + v3);
        }
    }
}

extern "C" void kernel_launch(void* const* d_in, const int* in_sizes, int n_in,
                              void* d_out, int out_size) {
    const float* feats = nullptr;
    const float* trans = nullptr;
    const void*  candA = nullptr;
    const void*  candB = nullptr;
    for (int i = 0; i < n_in; ++i) {
        long long c = in_sizes[i];
        if      (c == (long long)TT * BB * LLAB) feats = (const float*)d_in[i];
        else if (c == (long long)LLAB * LLAB)    trans = (const float*)d_in[i];
        else if (!candA)                         candA = d_in[i];
        else                                     candB = d_in[i];
    }

    crf_fused_kernel<<<BB, NT>>>(feats, trans, candA, candB, (float*)d_out);
}

// round 13
// speedup vs baseline: 1.2635x; 1.2635x over previous
#include <cuda_runtime.h>

// CRF negative log-likelihood, T=512 B=64 L=48, START=46, STOP=47.
// Fused kernel: buffer detection + gold score + forward recursion +
// last-block deterministic reduction.
//
// Forward recursion in linear space, rescaled every RESC steps by u[0]:
//   s_j  = sum_i u[i] * E[i][j],   E = exp(Tr)   (packed f32x2 FMAs)
//   u'[j]= s_j * exp(f_t[j]-f_t[0])   [ / u[0] on rescale steps ]
// 96 threads: 2 threads per state (half-dot = 24 elems each, shfl-combine).
// MUFU approx (ex2/lg2/rcp) for all transcendentals on the step path.
// Prefetch parity: slot k&1 holds f_{tb+k}; slot 0 <- t=1 at init.

#define TT 512
#define BB 64
#define LLAB 48
#define START_TAG 46
#define STOP_TAG 47
#define NT 96
#define RESC 8
#define L2E 1.4426950408889634f
#define LN2f 0.6931471805599453f
#define FSTRIDE (BB * LLAB)   // 3072 floats per time step

__device__ float        g_partial[BB];
__device__ unsigned int g_done;       // wraps 0..63 -> self-resetting

__device__ __forceinline__ float ex2_approx(float x) {
    float r; asm("ex2.approx.ftz.f32 %0, %1;" : "=f"(r) : "f"(x)); return r;
}
__device__ __forceinline__ float lg2_approx(float x) {
    float r; asm("lg2.approx.ftz.f32 %0, %1;" : "=f"(r) : "f"(x)); return r;
}
__device__ __forceinline__ float rcp_approx(float x) {
    float r; asm("rcp.approx.ftz.f32 %0, %1;" : "=f"(r) : "f"(x)); return r;
}

__device__ __forceinline__ int get_tag(const void* tags, int idx, int is32) {
    int v = is32 ? ((const int*)tags)[idx]
                 : (int)((const long long*)tags)[idx];
    return v < 0 ? 0 : (v > 47 ? 47 : v);
}
__device__ __forceinline__ int get_mask(const void* mask, int idx, int is8) {
    return is8 ? (int)((const unsigned char*)mask)[idx]
               : (((const int*)mask)[idx] != 0);
}

__global__ __launch_bounds__(NT, 1) void crf_fused_kernel(
    const float* __restrict__ feats,      // (T, B, L)
    const float* __restrict__ trans,      // (L, L)
    const void*  __restrict__ candA,
    const void*  __restrict__ candB,
    float*       __restrict__ out)
{
    const int b    = blockIdx.x;
    const int tid  = threadIdx.x;
    const int j    = tid >> 1;    // output state 0..47
    const int h    = tid & 1;     // half of the i-range
    const int w    = tid >> 5;
    const int lane = tid & 31;

    __shared__ __align__(16) float s_u[2][LLAB];
    __shared__ float s_gwarp[3];
    __shared__ float s_red[BB];
    __shared__ float s_gold;
    __shared__ int   s_len;
    __shared__ int   s_flags;
    __shared__ int   s_last;

    if (tid == 0) { s_len = 0; s_flags = 0; s_last = 0; }
    __syncthreads();

    // ---------------- buffer identification (one LDG round) ----------------
    {
        const unsigned* ua = (const unsigned*)candA;
        const unsigned* ub = (const unsigned*)candB;
        int f = 0;
        if (ua[tid] & 0xFEFEFEFEu)       f |= 1;   // A has byte >= 2 -> A=tags
        if (ub[tid] & 0xFEFEFEFEu)       f |= 2;
        if (ua[2 * tid + 1] != 0)        f |= 4;   // A odd words nonzero -> i32
        if (ub[2 * tid + 1] != 0)        f |= 8;
        if ((ua[0] & 0x0000FF00u) != 0)  f |= 16;  // 1-byte mask signature
        if ((ub[0] & 0x0000FF00u) != 0)  f |= 32;
        if (f) atomicOr(&s_flags, f);
    }
    __syncthreads();
    const int flags = s_flags;
    const int swap  = !(flags & 1);
    const void* tags = swap ? candB : candA;
    const void* mask = swap ? candA : candB;
    const int is32 = swap ? ((flags >> 3) & 1) : ((flags >> 2) & 1);
    const int is8  = swap ? ((flags >> 4) & 1) : ((flags >> 5) & 1);

    // ---------------- gold path score + length -----------------------------
    {
        float gpart = 0.0f;
        int   lpart = 0;
        for (int t = tid; t < TT; t += NT) {
            if (get_mask(mask, b * TT + t, is8)) {
                lpart++;
                int tag  = get_tag(tags, b * TT + t, is32);
                int prev = (t == 0) ? START_TAG : get_tag(tags, b * TT + t - 1, is32);
                gpart += feats[t * FSTRIDE + b * LLAB + tag]
                       + trans[prev * LLAB + tag];
            }
        }
        #pragma unroll
        for (int off = 16; off > 0; off >>= 1)
            gpart += __shfl_xor_sync(0xffffffffu, gpart, off);  // fixed order
        if (lane == 0) s_gwarp[w] = gpart;
        atomicAdd(&s_len, lpart);
    }

    // ------------- per-thread packed-E column slice (12 x f32x2 = 24 i) -----
    unsigned long long Epk[12];
    #pragma unroll
    for (int r = 0; r < 12; ++r) {
        float e0 = expf(trans[(24 * h + 2 * r)     * LLAB + j]);
        float e1 = expf(trans[(24 * h + 2 * r + 1) * LLAB + j]);
        unsigned long long pk;
        asm("mov.b64 %0, {%1, %2};" : "=l"(pk) : "f"(e0), "f"(e1));
        Epk[r] = pk;
    }

    // ---------------- init: p_0 = f_0 + Tr[START][:] ------------------------
    const float* fb = feats + b * LLAB;
    float p00 = fb[0] + trans[START_TAG * LLAB + 0];
    float p0j = fb[j] + trans[START_TAG * LLAB + j];
    if (h == 0) s_u[0][j] = ex2_approx((p0j - p00) * L2E);
    float Cacc  = p00;
    float Clog2 = 0.0f;

    __syncthreads();
    int len = s_len;
    len = len < 1 ? 1 : (len > TT ? TT : len);
    const int nsteps = len - 1;          // >= 255

    if (tid == 0) {
        int endid = get_tag(tags, b * TT + len - 1, is32);
        s_gold = (s_gwarp[0] + s_gwarp[1] + s_gwarp[2])
               + trans[endid * LLAB + STOP_TAG];
    }

    // ---------------- forward recursion --------------------------------------
    // Prefetch parity (FIXED): step t=tb+k consumes slot k&1.
    // Init: slot 0 <- f_{t=1} (k=0), slot 1 <- f_{t=2} (k=1).
    float pfj[2], pf0[2];
    {
        int t1 = (nsteps >= 1) ? 1 : 1;
        int t2 = (nsteps >= 2) ? 2 : t1;
        pfj[0] = fb[t1 * FSTRIDE + j];  pf0[0] = fb[t1 * FSTRIDE];
        pfj[1] = fb[t2 * FSTRIDE + j];  pf0[1] = fb[t2 * FSTRIDE];
    }

    const int npad = ((nsteps + RESC - 1) / RESC) * RESC;

    // tb starts at 1 and advances by RESC (even) -> tb odd always,
    // so (t-1)&1 == k&1: SMEM buffer parity is compile-time per k.
    for (int tb = 1; tb <= npad; tb += RESC) {
        #pragma unroll
        for (int k = 0; k < RESC; ++k) {
            const int  t    = tb + k;
            const bool live = (t <= nsteps);          // uniform across block

            int tp = t + 2; if (tp > nsteps) tp = nsteps; if (tp < 1) tp = 1;
            float nfj = fb[tp * FSTRIDE + j];
            float nf0 = fb[tp * FSTRIDE];

            float fj = pfj[k & 1], f0 = pf0[k & 1];
            float e  = ex2_approx((fj - f0) * L2E);   // pre-bar: hidden

            __syncthreads();                          // buf k&1 complete
            const float* uin  = s_u[k & 1];
            float*       uout = (float*)s_u[(k & 1) ^ 1];

            // u0 first: RCP/LG2 start ASAP, overlap with the dot
            float u0 = uin[0];                        // scalar broadcast LDS
            float er, lg = 0.0f;
            if (k == 0) {                             // rescale step
                float ru = rcp_approx(u0);
                lg = lg2_approx(u0);
                er = e * ru;
            } else {
                er = e;
            }

            // half-dot: 24 elems = 6x LDS.128 + 12 packed FMAs, depth 3
            unsigned long long a0 = 0ULL, a1 = 0ULL, a2 = 0ULL, a3 = 0ULL;
            const ulonglong2* up =
                reinterpret_cast<const ulonglong2*>(uin + 24 * h);
            ulonglong2 q0 = up[0];
            ulonglong2 q1 = up[1];
            ulonglong2 q2 = up[2];
            ulonglong2 q3 = up[3];
            ulonglong2 q4 = up[4];
            ulonglong2 q5 = up[5];
            asm("fma.rn.f32x2 %0, %1, %2, %0;" : "+l"(a0) : "l"(q0.x), "l"(Epk[0]));
            asm("fma.rn.f32x2 %0, %1, %2, %0;" : "+l"(a1) : "l"(q0.y), "l"(Epk[1]));
            asm("fma.rn.f32x2 %0, %1, %2, %0;" : "+l"(a2) : "l"(q1.x), "l"(Epk[2]));
            asm("fma.rn.f32x2 %0, %1, %2, %0;" : "+l"(a3) : "l"(q1.y), "l"(Epk[3]));
            asm("fma.rn.f32x2 %0, %1, %2, %0;" : "+l"(a0) : "l"(q2.x), "l"(Epk[4]));
            asm("fma.rn.f32x2 %0, %1, %2, %0;" : "+l"(a1) : "l"(q2.y), "l"(Epk[5]));
            asm("fma.rn.f32x2 %0, %1, %2, %0;" : "+l"(a2) : "l"(q3.x), "l"(Epk[6]));
            asm("fma.rn.f32x2 %0, %1, %2, %0;" : "+l"(a3) : "l"(q3.y), "l"(Epk[7]));
            asm("fma.rn.f32x2 %0, %1, %2, %0;" : "+l"(a0) : "l"(q4.x), "l"(Epk[8]));
            asm("fma.rn.f32x2 %0, %1, %2, %0;" : "+l"(a1) : "l"(q4.y), "l"(Epk[9]));
            asm("fma.rn.f32x2 %0, %1, %2, %0;" : "+l"(a2) : "l"(q5.x), "l"(Epk[10]));
            asm("fma.rn.f32x2 %0, %1, %2, %0;" : "+l"(a3) : "l"(q5.y), "l"(Epk[11]));

            unsigned long long s01, s23, sall;
            asm("add.rn.f32x2 %0, %1, %2;" : "=l"(s01)  : "l"(a0), "l"(a1));
            asm("add.rn.f32x2 %0, %1, %2;" : "=l"(s23)  : "l"(a2), "l"(a3));
            asm("add.rn.f32x2 %0, %1, %2;" : "=l"(sall) : "l"(s01), "l"(s23));
            float slo, shi;
            asm("mov.b64 {%0, %1}, %2;" : "=f"(slo), "=f"(shi) : "l"(sall));
            float s = slo + shi;
            s += __shfl_xor_sync(0xffffffffu, s, 1);  // combine halves

            float unew = s * er;                      // single FMUL after shfl
            if (h == 0 && live) uout[j] = unew;

            if (live) {                               // off critical path
                Cacc += f0;
                if (k == 0) Clog2 += lg;
            }
            pfj[k & 1] = nfj; pf0[k & 1] = nf0;
        }
    }

    __syncthreads();

    // -------- final transition to STOP (single thread, off clock) -----------
    if (tid == 94) {                 // (j=47, h=0)
        const float* uin = s_u[(len - 1) & 1];
        float a0 = 0.f, a1 = 0.f, a2 = 0.f, a3 = 0.f;
        #pragma unroll
        for (int i = 0; i < LLAB; i += 4) {
            a0 = fmaf(uin[i + 0], expf(trans[(i + 0) * LLAB + STOP_TAG]), a0);
            a1 = fmaf(uin[i + 1], expf(trans[(i + 1) * LLAB + STOP_TAG]), a1);
            a2 = fmaf(uin[i + 2], expf(trans[(i + 2) * LLAB + STOP_TAG]), a2);
            a3 = fmaf(uin[i + 3], expf(trans[(i + 3) * LLAB + STOP_TAG]), a3);
        }
        float s = (a0 + a1) + (a2 + a3);
        float fwd = Cacc + (Clog2 + lg2_approx(s)) * LN2f;
        g_partial[b] = fwd - s_gold;
        __threadfence();
        if (atomicInc(&g_done, BB - 1) == BB - 1) s_last = 1;
    }
    __syncthreads();

    // ---------------- last block: deterministic fixed-order reduction -------
    if (s_last) {
        if (tid < BB) s_red[tid] = __ldcg(&g_partial[tid]);
        __syncthreads();
        if (tid == 0) {
            float v0 = 0.f, v1 = 0.f, v2 = 0.f, v3 = 0.f;
            #pragma unroll
            for (int i = 0; i < BB; i += 4) {
                v0 += s_red[i + 0];
                v1 += s_red[i + 1];
                v2 += s_red[i + 2];
                v3 += s_red[i + 3];
            }
            out[0] = (v0 + v1) + (v2 + v3);
        }
    }
}

extern "C" void kernel_launch(void* const* d_in, const int* in_sizes, int n_in,
                              void* d_out, int out_size) {
    const float* feats = nullptr;
    const float* trans = nullptr;
    const void*  candA = nullptr;
    const void*  candB = nullptr;
    for (int i = 0; i < n_in; ++i) {
        long long c = in_sizes[i];
        if      (c == (long long)TT * BB * LLAB) feats = (const float*)d_in[i];
        else if (c == (long long)LLAB * LLAB)    trans = (const float*)d_in[i];
        else if (!candA)                         candA = d_in[i];
        else                                     candB = d_in[i];
    }

    crf_fused_kernel<<<BB, NT>>>(feats, trans, candA, candB, (float*)d_out);
}

// round 14
// speedup vs baseline: 1.7779x; 1.4072x over previous
#include <cuda_runtime.h>

// CRF negative log-likelihood, T=512 B=64 L=48, START=46, STOP=47.
// Fused kernel: buffer detection + gold score + forward recursion +
// last-block deterministic reduction.
//
// Forward recursion in linear space, rescaled every RESC steps by u[0]:
//   s_j  = sum_i u[i] * E[i][j],   E = exp(Tr)   (packed f32x2 FMAs)
//   u'[j]= s_j * exp(f_t[j]-f_t[0])   [ / u[0] on rescale steps ]
// 96 threads: 2 threads per state (half-dot = 24 elems each, shfl-combine).
// MUFU approx (ex2/lg2/rcp) on the step path.
// CHAMPION BODY (R9, 55.9us) + prefetch-parity fix ONLY:
//   step t=tb+k consumes feats slot k&1; init slot 0 <- f_{t=1}.

#define TT 512
#define BB 64
#define LLAB 48
#define START_TAG 46
#define STOP_TAG 47
#define NT 96
#define RESC 8
#define L2E 1.4426950408889634f
#define LN2f 0.6931471805599453f
#define FSTRIDE (BB * LLAB)   // 3072 floats per time step

__device__ float        g_partial[BB];
__device__ unsigned int g_done;       // wraps 0..63 -> self-resetting

__device__ __forceinline__ float ex2_approx(float x) {
    float r; asm("ex2.approx.ftz.f32 %0, %1;" : "=f"(r) : "f"(x)); return r;
}
__device__ __forceinline__ float lg2_approx(float x) {
    float r; asm("lg2.approx.ftz.f32 %0, %1;" : "=f"(r) : "f"(x)); return r;
}
__device__ __forceinline__ float rcp_approx(float x) {
    float r; asm("rcp.approx.ftz.f32 %0, %1;" : "=f"(r) : "f"(x)); return r;
}

__device__ __forceinline__ int get_tag(const void* tags, int idx, int is32) {
    int v = is32 ? ((const int*)tags)[idx]
                 : (int)((const long long*)tags)[idx];
    return v < 0 ? 0 : (v > 47 ? 47 : v);
}
__device__ __forceinline__ int get_mask(const void* mask, int idx, int is8) {
    return is8 ? (int)((const unsigned char*)mask)[idx]
               : (((const int*)mask)[idx] != 0);
}

__global__ __launch_bounds__(NT, 1) void crf_fused_kernel(
    const float* __restrict__ feats,      // (T, B, L)
    const float* __restrict__ trans,      // (L, L)
    const void*  __restrict__ candA,
    const void*  __restrict__ candB,
    float*       __restrict__ out)
{
    const int b    = blockIdx.x;
    const int tid  = threadIdx.x;
    const int j    = tid >> 1;    // output state 0..47
    const int h    = tid & 1;     // half of the i-range
    const int w    = tid >> 5;
    const int lane = tid & 31;

    __shared__ __align__(16) float s_u[2][LLAB];
    __shared__ float s_gwarp[3];
    __shared__ float s_red[BB];
    __shared__ float s_gold;
    __shared__ int   s_len;
    __shared__ int   s_flags;
    __shared__ int   s_last;

    if (tid == 0) { s_len = 0; s_flags = 0; s_last = 0; }
    __syncthreads();

    // ---------------- buffer identification (one LDG round) ----------------
    {
        const unsigned* ua = (const unsigned*)candA;
        const unsigned* ub = (const unsigned*)candB;
        int f = 0;
        if (ua[tid] & 0xFEFEFEFEu)       f |= 1;   // A has byte >= 2 -> A=tags
        if (ub[tid] & 0xFEFEFEFEu)       f |= 2;
        if (ua[2 * tid + 1] != 0)        f |= 4;   // A odd words nonzero -> i32
        if (ub[2 * tid + 1] != 0)        f |= 8;
        if ((ua[0] & 0x0000FF00u) != 0)  f |= 16;  // 1-byte mask signature
        if ((ub[0] & 0x0000FF00u) != 0)  f |= 32;
        if (f) atomicOr(&s_flags, f);
    }
    __syncthreads();
    const int flags = s_flags;
    const int swap  = !(flags & 1);
    const void* tags = swap ? candB : candA;
    const void* mask = swap ? candA : candB;
    const int is32 = swap ? ((flags >> 3) & 1) : ((flags >> 2) & 1);
    const int is8  = swap ? ((flags >> 4) & 1) : ((flags >> 5) & 1);

    // ---------------- gold path score + length -----------------------------
    {
        float gpart = 0.0f;
        int   lpart = 0;
        for (int t = tid; t < TT; t += NT) {
            if (get_mask(mask, b * TT + t, is8)) {
                lpart++;
                int tag  = get_tag(tags, b * TT + t, is32);
                int prev = (t == 0) ? START_TAG : get_tag(tags, b * TT + t - 1, is32);
                gpart += feats[t * FSTRIDE + b * LLAB + tag]
                       + trans[prev * LLAB + tag];
            }
        }
        #pragma unroll
        for (int off = 16; off > 0; off >>= 1)
            gpart += __shfl_xor_sync(0xffffffffu, gpart, off);  // fixed order
        if (lane == 0) s_gwarp[w] = gpart;
        atomicAdd(&s_len, lpart);
    }

    // ------------- per-thread packed-E column slice (12 x f32x2 = 24 i) -----
    unsigned long long Epk[12];
    #pragma unroll
    for (int r = 0; r < 12; ++r) {
        float e0 = expf(trans[(24 * h + 2 * r)     * LLAB + j]);
        float e1 = expf(trans[(24 * h + 2 * r + 1) * LLAB + j]);
        unsigned long long pk;
        asm("mov.b64 %0, {%1, %2};" : "=l"(pk) : "f"(e0), "f"(e1));
        Epk[r] = pk;
    }

    // ---------------- init: p_0 = f_0 + Tr[START][:] ------------------------
    const float* fb = feats + b * LLAB;
    float p00 = fb[0] + trans[START_TAG * LLAB + 0];
    float p0j = fb[j] + trans[START_TAG * LLAB + j];
    if (h == 0) s_u[0][j] = ex2_approx((p0j - p00) * L2E);
    float Cacc  = p00;
    float Clog2 = 0.0f;

    __syncthreads();
    int len = s_len;
    len = len < 1 ? 1 : (len > TT ? TT : len);
    const int nsteps = len - 1;          // >= 255

    if (tid == 0) {
        int endid = get_tag(tags, b * TT + len - 1, is32);
        s_gold = (s_gwarp[0] + s_gwarp[1] + s_gwarp[2])
               + trans[endid * LLAB + STOP_TAG];
    }

    // ---------------- forward recursion --------------------------------------
    // Prefetch parity (FIXED): step t=tb+k consumes slot k&1.
    // Init: slot 0 <- f_{t=1}, slot 1 <- f_{t=2}.
    float pfj[2], pf0[2];
    {
        int t1 = 1;
        int t2 = (2 <= nsteps) ? 2 : t1;
        pfj[0] = fb[t1 * FSTRIDE + j];  pf0[0] = fb[t1 * FSTRIDE];
        pfj[1] = fb[t2 * FSTRIDE + j];  pf0[1] = fb[t2 * FSTRIDE];
    }

    const int npad = ((nsteps + RESC - 1) / RESC) * RESC;

    // tb starts at 1 and advances by RESC (even) -> tb odd always,
    // so (t-1)&1 == k&1: SMEM buffer parity is compile-time per k.
    for (int tb = 1; tb <= npad; tb += RESC) {
        #pragma unroll
        for (int k = 0; k < RESC; ++k) {
            const int  t    = tb + k;
            const bool live = (t <= nsteps);          // uniform across block

            int tp = t + 2; if (tp > nsteps) tp = nsteps;
            float nfj = fb[tp * FSTRIDE + j];
            float nf0 = fb[tp * FSTRIDE];

            float fj = pfj[k & 1], f0 = pf0[k & 1];
            float e  = ex2_approx((fj - f0) * L2E);   // pre-bar: hidden

            __syncthreads();                          // buf k&1 complete
            const float* uin  = s_u[k & 1];
            float*       uout = (float*)s_u[(k & 1) ^ 1];

            // half-dot: 24 elems = 6x LDS.128 + 12 packed FMAs, depth 3
            unsigned long long a0 = 0ULL, a1 = 0ULL, a2 = 0ULL, a3 = 0ULL;
            const ulonglong2* up =
                reinterpret_cast<const ulonglong2*>(uin + 24 * h);
            ulonglong2 q0 = up[0];
            ulonglong2 q1 = up[1];
            ulonglong2 q2 = up[2];
            ulonglong2 q3 = up[3];
            ulonglong2 q4 = up[4];
            ulonglong2 q5 = up[5];
            asm("fma.rn.f32x2 %0, %1, %2, %0;" : "+l"(a0) : "l"(q0.x), "l"(Epk[0]));
            asm("fma.rn.f32x2 %0, %1, %2, %0;" : "+l"(a1) : "l"(q0.y), "l"(Epk[1]));
            asm("fma.rn.f32x2 %0, %1, %2, %0;" : "+l"(a2) : "l"(q1.x), "l"(Epk[2]));
            asm("fma.rn.f32x2 %0, %1, %2, %0;" : "+l"(a3) : "l"(q1.y), "l"(Epk[3]));
            asm("fma.rn.f32x2 %0, %1, %2, %0;" : "+l"(a0) : "l"(q2.x), "l"(Epk[4]));
            asm("fma.rn.f32x2 %0, %1, %2, %0;" : "+l"(a1) : "l"(q2.y), "l"(Epk[5]));
            asm("fma.rn.f32x2 %0, %1, %2, %0;" : "+l"(a2) : "l"(q3.x), "l"(Epk[6]));
            asm("fma.rn.f32x2 %0, %1, %2, %0;" : "+l"(a3) : "l"(q3.y), "l"(Epk[7]));
            asm("fma.rn.f32x2 %0, %1, %2, %0;" : "+l"(a0) : "l"(q4.x), "l"(Epk[8]));
            asm("fma.rn.f32x2 %0, %1, %2, %0;" : "+l"(a1) : "l"(q4.y), "l"(Epk[9]));
            asm("fma.rn.f32x2 %0, %1, %2, %0;" : "+l"(a2) : "l"(q5.x), "l"(Epk[10]));
            asm("fma.rn.f32x2 %0, %1, %2, %0;" : "+l"(a3) : "l"(q5.y), "l"(Epk[11]));

            float u0 = uin[0];                        // scalar broadcast LDS
            float ru = 1.0f, lg = 0.0f;
            if (k == 0) {                             // rescale step
                ru = rcp_approx(u0);
                lg = lg2_approx(u0);
            }

            unsigned long long s01, s23, sall;
            asm("add.rn.f32x2 %0, %1, %2;" : "=l"(s01)  : "l"(a0), "l"(a1));
            asm("add.rn.f32x2 %0, %1, %2;" : "=l"(s23)  : "l"(a2), "l"(a3));
            asm("add.rn.f32x2 %0, %1, %2;" : "=l"(sall) : "l"(s01), "l"(s23));
            float slo, shi;
            asm("mov.b64 {%0, %1}, %2;" : "=f"(slo), "=f"(shi) : "l"(sall));
            float s = slo + shi;
            s += __shfl_xor_sync(0xffffffffu, s, 1);  // combine halves

            float unew = (k == 0) ? s * e * ru : s * e;
            if (h == 0 && live) uout[j] = unew;

            if (live) {                               // off critical path
                Cacc += f0;
                if (k == 0) Clog2 += lg;
            }
            pfj[k & 1] = nfj; pf0[k & 1] = nf0;
        }
    }

    __syncthreads();

    // -------- final transition to STOP (single thread, off clock) -----------
    if (tid == 94) {                 // (j=47, h=0)
        const float* uin = s_u[(len - 1) & 1];
        float a0 = 0.f, a1 = 0.f, a2 = 0.f, a3 = 0.f;
        #pragma unroll
        for (int i = 0; i < LLAB; i += 4) {
            a0 = fmaf(uin[i + 0], expf(trans[(i + 0) * LLAB + STOP_TAG]), a0);
            a1 = fmaf(uin[i + 1], expf(trans[(i + 1) * LLAB + STOP_TAG]), a1);
            a2 = fmaf(uin[i + 2], expf(trans[(i + 2) * LLAB + STOP_TAG]), a2);
            a3 = fmaf(uin[i + 3], expf(trans[(i + 3) * LLAB + STOP_TAG]), a3);
        }
        float s = (a0 + a1) + (a2 + a3);
        float fwd = Cacc + (Clog2 + lg2_approx(s)) * LN2f;
        g_partial[b] = fwd - s_gold;
        __threadfence();
        if (atomicInc(&g_done, BB - 1) == BB - 1) s_last = 1;
    }
    __syncthreads();

    // ---------------- last block: deterministic fixed-order reduction -------
    if (s_last) {
        if (tid < BB) s_red[tid] = __ldcg(&g_partial[tid]);
        __syncthreads();
        if (tid == 0) {
            float v0 = 0.f, v1 = 0.f, v2 = 0.f, v3 = 0.f;
            #pragma unroll
            for (int i = 0; i < BB; i += 4) {
                v0 += s_red[i + 0];
                v1 += s_red[i + 1];
                v2 += s_red[i + 2];
                v3 += s_red[i + 3];
            }
            out[0] = (v0 + v1) + (v2 + v3);
        }
    }
}

extern "C" void kernel_launch(void* const* d_in, const int* in_sizes, int n_in,
                              void* d_out, int out_size) {
    const float* feats = nullptr;
    const float* trans = nullptr;
    const void*  candA = nullptr;
    const void*  candB = nullptr;
    for (int i = 0; i < n_in; ++i) {
        long long c = in_sizes[i];
        if      (c == (long long)TT * BB * LLAB) feats = (const float*)d_in[i];
        else if (c == (long long)LLAB * LLAB)    trans = (const float*)d_in[i];
        else if (!candA)                         candA = d_in[i];
        else                                     candB = d_in[i];
    }

    crf_fused_kernel<<<BB, NT>>>(feats, trans, candA, candB, (float*)d_out);
}